// round 7
// baseline (speedup 1.0000x reference)
#include <cuda_runtime.h>
#include <cuda_bf16.h>
#include <cstdint>
#include <cstddef>

#define BATCH 512
#define NIN   2048
#define UNITS 4096
#define KTOT  6144
#define OFS   (BATCH*UNITS)

#define BM 128
#define BN 128
#define BK 128
#define STAGES 3
#define NKS (KTOT/BK)          // 48 ; stages 0..15 = Win, 16..47 = Wrec
#define TILE_BYTES 32768u      // 128 rows x 256 B
#define STAGE_BYTES 65536u
#define GEMM_SMEM (STAGES*STAGE_BYTES + 1024u)

#define SWZB(x) ((x) ^ (((x) >> 4) & 0x70u))

#define NPKB (BATCH*KTOT/512)  // 6144
#define NDGB (UNITS/256)       // 16

#define C_EL      (-70.6f)
#define C_THR     (-50.4f)
#define C_DTGLC   ((float)(30.0/281.0))
#define C_INVCAP  ((float)(1.0/281.0))
#define C_DTTAUW  ((float)(1.0/144.0))
#define C_DTATAUW ((float)(4.0/144.0))
#define C_BW      (0.0805f)
#define C_VRST    (-70.6f)
#define C_CLIP    (281.0f)

__device__ __nv_bfloat16 g_Apack[(size_t)BATCH * KTOT];
__device__ float g_diag[UNITS];

__device__ __forceinline__ uint32_t smem_u32(const void* p) {
    uint32_t a;
    asm("{ .reg .u64 t; cvta.to.shared.u64 t, %1; cvt.u32.u64 %0, t; }"
        : "=r"(a) : "l"(p));
    return a;
}
__device__ __forceinline__ void cp16(uint32_t saddr, const void* g) {
    asm volatile("cp.async.cg.shared.global [%0], [%1], 16;"
                 :: "r"(saddr), "l"(g));
}
__device__ __forceinline__ void ldmx4(uint32_t& r0, uint32_t& r1,
                                      uint32_t& r2, uint32_t& r3, uint32_t a) {
    asm volatile("ldmatrix.sync.aligned.m8n8.x4.shared.b16 {%0,%1,%2,%3}, [%4];"
                 : "=r"(r0), "=r"(r1), "=r"(r2), "=r"(r3) : "r"(a));
}
__device__ __forceinline__ void ldmx4t(uint32_t& r0, uint32_t& r1,
                                       uint32_t& r2, uint32_t& r3, uint32_t a) {
    asm volatile("ldmatrix.sync.aligned.m8n8.x4.trans.shared.b16 {%0,%1,%2,%3}, [%4];"
                 : "=r"(r0), "=r"(r1), "=r"(r2), "=r"(r3) : "r"(a));
}
__device__ __forceinline__ void mma16816(float& d0, float& d1, float& d2, float& d3,
                                         uint32_t a0, uint32_t a1, uint32_t a2, uint32_t a3,
                                         uint32_t b0, uint32_t b1) {
    asm volatile(
        "mma.sync.aligned.m16n8k16.row.col.f32.bf16.bf16.f32 "
        "{%0,%1,%2,%3}, {%4,%5,%6,%7}, {%8,%9}, {%0,%1,%2,%3};"
        : "+f"(d0), "+f"(d1), "+f"(d2), "+f"(d3)
        : "r"(a0), "r"(a1), "r"(a2), "r"(a3), "r"(b0), "r"(b1));
}

// ---------------- prep: pack A, extract diag (W stays fp32 in gmem) -------
__global__ void __launch_bounds__(256)
prep_kernel(const float* __restrict__ inp, const float* __restrict__ z,
            const float* __restrict__ Wrec) {
    int blk = blockIdx.x;
    int tid = threadIdx.x;
    if (blk < NPKB) {
        int idx = blk * 256 + tid;
        int b = idx / (KTOT / 2);
        int c = idx - b * (KTOT / 2);
        int k = 2 * c;
        float x0, x1;
        if (k < NIN) {
            const float* p = inp + (size_t)b * NIN + k;
            x0 = p[0]; x1 = p[1];
        } else {
            const float* p = z + (size_t)b * UNITS + (k - NIN);
            x0 = p[0]; x1 = p[1];
        }
        reinterpret_cast<__nv_bfloat162*>(g_Apack)[idx] = __floats2bfloat162_rn(x0, x1);
    } else {
        int n = (blk - NPKB) * 256 + tid;
        g_diag[n] = __bfloat162float(__float2bfloat16(Wrec[(size_t)n * UNITS + n]));
    }
}

// ---------------- A-stage loader (cp.async, bf16) ----------------
__device__ __forceinline__ void load_stage_A(uint32_t tiles, int tid,
                                             const __nv_bfloat16* Ag,
                                             int ks, int s) {
    uint32_t abase = tiles + (uint32_t)s * STAGE_BYTES;
    const __nv_bfloat16* ag = Ag + ks * BK;
    #pragma unroll
    for (int i = 0; i < 8; i++) {
        int id = tid + i * 256;
        int row = id >> 4, cg = id & 15;
        uint32_t off = SWZB((uint32_t)(row * 256 + cg * 16));
        cp16(abase + off, ag + (size_t)row * KTOT + cg * 8);
    }
}

// ---------------- B produce: LDG fp32 -> regs ----------------
// thread t: k-row = t>>1, half h = t&1, chunks c = h + 2i (i=0..7), 8 n each
__device__ __forceinline__ void ldg_B(float4* rv, int ks, int tid, int n0,
                                      const float* __restrict__ Win,
                                      const float* __restrict__ Wrec) {
    int row = tid >> 1, h = tid & 1;
    const float* src = (ks < 16)
        ? (Win  + (size_t)(ks * BK + row) * UNITS + n0)
        : (Wrec + (size_t)(ks * BK - NIN + row) * UNITS + n0);
    #pragma unroll
    for (int i = 0; i < 8; i++) {
        int c = h + 2 * i;
        rv[2 * i]     = *reinterpret_cast<const float4*>(src + c * 8);
        rv[2 * i + 1] = *reinterpret_cast<const float4*>(src + c * 8 + 4);
    }
}
// cvt + STS.128 into swizzled bf16 B tile
__device__ __forceinline__ void sts_B(const float4* rv, uint32_t bbase, int tid) {
    int row = tid >> 1, h = tid & 1;
    #pragma unroll
    for (int i = 0; i < 8; i++) {
        int c = h + 2 * i;
        __nv_bfloat162 q0 = __floats2bfloat162_rn(rv[2*i].x,   rv[2*i].y);
        __nv_bfloat162 q1 = __floats2bfloat162_rn(rv[2*i].z,   rv[2*i].w);
        __nv_bfloat162 q2 = __floats2bfloat162_rn(rv[2*i+1].x, rv[2*i+1].y);
        __nv_bfloat162 q3 = __floats2bfloat162_rn(rv[2*i+1].z, rv[2*i+1].w);
        uint32_t addr = bbase + SWZB((uint32_t)(row * 256 + c * 16));
        asm volatile("st.shared.v4.b32 [%0], {%1,%2,%3,%4};"
                     :: "r"(addr),
                        "r"(*reinterpret_cast<uint32_t*>(&q0)),
                        "r"(*reinterpret_cast<uint32_t*>(&q1)),
                        "r"(*reinterpret_cast<uint32_t*>(&q2)),
                        "r"(*reinterpret_cast<uint32_t*>(&q3)) : "memory");
    }
}

// ---------------- AdEx elementwise ----------------
__device__ __forceinline__ void adex_one(float it, float vo, float wo, float zo,
                                         int ro, float& nv, float& nz,
                                         float& nw, float& nr) {
    float ex = expf((vo - C_THR) * 0.5f);
    ex = fminf(ex, C_CLIP);
    float nv0 = vo - C_DTGLC * (vo - C_EL) + (2.0f * C_DTGLC) * ex
              + (it - wo) * C_INVCAP;
    nv = (zo > 0.5f) ? C_VRST : nv0;
    nw = wo - wo * C_DTTAUW + C_DTATAUW * (vo - C_EL) + C_BW * zo;
    bool sp = (nv > C_THR) && (ro <= 0);
    nz = sp ? 1.0f : 0.0f;
    int nri = ro - 1 + (sp ? 2 : 0);
    nri = nri < 0 ? 0 : (nri > 2 ? 2 : nri);
    nr = (float)nri;
}

// ---------------- GEMM + fused W-convert + AdEx epilogue ----------------
__global__ void __launch_bounds__(256, 1)
adex_gemm_kernel(const float* __restrict__ v_in, const int* __restrict__ r_in,
                 const float* __restrict__ w_in, const float* __restrict__ z_in,
                 const float* __restrict__ Win, const float* __restrict__ Wrec,
                 float* __restrict__ out) {
    extern __shared__ char smem[];
    uint32_t tiles = (smem_u32(smem) + 1023u) & ~1023u;
    int tid = threadIdx.x;
    int wid = tid >> 5;
    int lane = tid & 31;

    int m0 = (blockIdx.x & 3) * BM;
    int n0 = (blockIdx.x >> 2) * BN;
    int wm = (wid & 1) * 64;
    int wn = (wid >> 1) * 32;

    const __nv_bfloat16* Ag = g_Apack + (size_t)m0 * KTOT;

    float acc[4][4][4];
    #pragma unroll
    for (int i = 0; i < 4; i++)
        #pragma unroll
        for (int j = 0; j < 4; j++)
            #pragma unroll
            for (int q = 0; q < 4; q++) acc[i][j][q] = 0.0f;

    // prologue: stages 0,1 (A async; B synchronous LDG->STS)
    {
        float4 rv[16];
        load_stage_A(tiles, tid, Ag, 0, 0);
        asm volatile("cp.async.commit_group;");
        ldg_B(rv, 0, tid, n0, Win, Wrec);
        sts_B(rv, tiles + 0 * STAGE_BYTES + TILE_BYTES, tid);
        load_stage_A(tiles, tid, Ag, 1, 1);
        asm volatile("cp.async.commit_group;");
        ldg_B(rv, 1, tid, n0, Win, Wrec);
        sts_B(rv, tiles + 1 * STAGE_BYTES + TILE_BYTES, tid);
    }

    int lrow = lane & 15;
    int lcg  = (lane >> 4) * 16;

    uint32_t aoff[4];
    #pragma unroll
    for (int mf = 0; mf < 4; ++mf)
        aoff[mf] = (uint32_t)((wm + mf * 16 + lrow) * 256 + lcg);
    uint32_t boff[2];
    #pragma unroll
    for (int p = 0; p < 2; ++p)
        boff[p] = (uint32_t)(lrow * 256 + wn * 2 + p * 32 + lcg);

    int s = 0, sn = STAGES - 1;
    for (int ks = 0; ks < NKS; ++ks) {
        asm volatile("cp.async.wait_group %0;" :: "n"(1));
        __syncthreads();

        // issue next-stage loads: A via cp.async, B fp32 LDGs into regs
        int kn = ks + STAGES - 1;
        float4 rv[16];
        if (kn < NKS) {
            load_stage_A(tiles, tid, Ag, kn, sn);
            ldg_B(rv, kn, tid, n0, Win, Wrec);
        }
        asm volatile("cp.async.commit_group;");

        uint32_t abase = tiles + (uint32_t)s * STAGE_BYTES;
        uint32_t bbase = abase + TILE_BYTES;

        uint32_t af[2][4][4], bfr[2][4][2];

        #pragma unroll
        for (int mf = 0; mf < 4; ++mf)
            ldmx4(af[0][mf][0], af[0][mf][1], af[0][mf][2], af[0][mf][3],
                  abase + SWZB(aoff[mf]));
        #pragma unroll
        for (int p = 0; p < 2; ++p) {
            uint32_t r0, r1, r2, r3;
            ldmx4t(r0, r1, r2, r3, bbase + SWZB(boff[p]));
            bfr[0][p * 2 + 0][0] = r0; bfr[0][p * 2 + 0][1] = r1;
            bfr[0][p * 2 + 1][0] = r2; bfr[0][p * 2 + 1][1] = r3;
        }

        #pragma unroll
        for (int kk = 0; kk < BK / 16; ++kk) {
            int cur = kk & 1, nxt = cur ^ 1;
            if (kk < BK / 16 - 1) {
                uint32_t kba = (uint32_t)((kk + 1) * 32);
                uint32_t kbb = (uint32_t)((kk + 1) * 4096);
                #pragma unroll
                for (int mf = 0; mf < 4; ++mf)
                    ldmx4(af[nxt][mf][0], af[nxt][mf][1],
                          af[nxt][mf][2], af[nxt][mf][3],
                          abase + SWZB(aoff[mf] + kba));
                #pragma unroll
                for (int p = 0; p < 2; ++p) {
                    uint32_t r0, r1, r2, r3;
                    ldmx4t(r0, r1, r2, r3, bbase + SWZB(boff[p] + kbb));
                    bfr[nxt][p * 2 + 0][0] = r0; bfr[nxt][p * 2 + 0][1] = r1;
                    bfr[nxt][p * 2 + 1][0] = r2; bfr[nxt][p * 2 + 1][1] = r3;
                }
            }
            #pragma unroll
            for (int mf = 0; mf < 4; ++mf)
                #pragma unroll
                for (int nf = 0; nf < 4; ++nf)
                    mma16816(acc[mf][nf][0], acc[mf][nf][1],
                             acc[mf][nf][2], acc[mf][nf][3],
                             af[cur][mf][0], af[cur][mf][1],
                             af[cur][mf][2], af[cur][mf][3],
                             bfr[cur][nf][0], bfr[cur][nf][1]);
        }

        // store next stage's B (LDG results have had the compute loop to land)
        if (kn < NKS)
            sts_B(rv, tiles + (uint32_t)sn * STAGE_BYTES + TILE_BYTES, tid);

        s = (s + 1 == STAGES) ? 0 : s + 1;
        sn = (sn + 1 == STAGES) ? 0 : sn + 1;
    }

    // ------------- epilogue -------------
    int gid = lane >> 2;
    int qn  = (lane & 3) * 2;

    #pragma unroll
    for (int mf = 0; mf < 4; ++mf) {
        #pragma unroll
        for (int g = 0; g < 2; ++g) {
            int b = m0 + wm + mf * 16 + g * 8 + gid;
            size_t rowbase = (size_t)b * UNITS + n0 + wn;
            #pragma unroll
            for (int nf = 0; nf < 4; ++nf) {
                size_t ofs = rowbase + nf * 8 + qn;
                int ncol = n0 + wn + nf * 8 + qn;
                float2 vv = *reinterpret_cast<const float2*>(v_in + ofs);
                float2 ww = *reinterpret_cast<const float2*>(w_in + ofs);
                float2 zz = *reinterpret_cast<const float2*>(z_in + ofs);
                int2   rr = *reinterpret_cast<const int2*>(r_in + ofs);
                float2 dg = *reinterpret_cast<const float2*>(g_diag + ncol);
                float i0 = acc[mf][nf][g * 2 + 0] - zz.x * dg.x;
                float i1 = acc[mf][nf][g * 2 + 1] - zz.y * dg.y;
                float2 ov, oz, ow, orr;
                adex_one(i0, vv.x, ww.x, zz.x, rr.x, ov.x, oz.x, ow.x, orr.x);
                adex_one(i1, vv.y, ww.y, zz.y, rr.y, ov.y, oz.y, ow.y, orr.y);
                *reinterpret_cast<float2*>(out + 0 * (size_t)OFS + ofs) = ov;
                *reinterpret_cast<float2*>(out + 1 * (size_t)OFS + ofs) = oz;
                *reinterpret_cast<float2*>(out + 2 * (size_t)OFS + ofs) = ow;
                *reinterpret_cast<float2*>(out + 3 * (size_t)OFS + ofs) = orr;
            }
        }
    }
}

extern "C" void kernel_launch(void* const* d_in, const int* in_sizes, int n_in,
                              void* d_out, int out_size) {
    const float* inputs = (const float*)d_in[0];
    const float* v      = (const float*)d_in[1];
    const int*   r      = (const int*)d_in[2];
    const float* w      = (const float*)d_in[3];
    const float* z      = (const float*)d_in[4];
    const float* Win    = (const float*)d_in[5];
    const float* Wrec   = (const float*)d_in[6];
    float* out = (float*)d_out;
    (void)in_sizes; (void)n_in; (void)out_size;

    cudaFuncSetAttribute(adex_gemm_kernel,
                         cudaFuncAttributeMaxDynamicSharedMemorySize, GEMM_SMEM);

    prep_kernel<<<NPKB + NDGB, 256>>>(inputs, z, Wrec);
    adex_gemm_kernel<<<128, 256, GEMM_SMEM>>>(v, r, w, z, Win, Wrec, out);
}